// round 3
// baseline (speedup 1.0000x reference)
#include <cuda_runtime.h>
#include <stdint.h>

// Problem constants
#define BATCH 4
#define NPTS  65536     // power of two: >>16 / &0xFFFF tricks
#define KNB   16
#define HID   64

// Scratch: xyz-interleaved positions (float4 = xyz + pad) for 1-load gathers.
// 4 * 65536 * 16B = 16.75 MB -> L2-resident on GB300 (126 MB L2).
__device__ float4 g_pos_t[BATCH * NPTS];

// idx dtype flag: 1 if the idx buffer is genuine int64, 0 if int32.
__device__ int g_idx_is_i64;

// ---------------------------------------------------------------------------
// Kernel 0: probe idx dtype. Values lie in [0, 65536), so if the buffer is
// little-endian int64, every odd 32-bit word (the high half) is zero. If it is
// int32, odd words are ordinary indices (all-zero across 1024 samples has
// probability ~(1/65536)^1024 ~= 0). Reads only the first 8 KB -> in-bounds
// under either dtype. Deterministic per input -> graph-safe.
// ---------------------------------------------------------------------------
__global__ void probe_idx_dtype_kernel(const int* __restrict__ idx_as_i32) {
    int t = threadIdx.x;
    int nz = 0;
    #pragma unroll
    for (int i = t; i < 1024; i += 256) nz |= idx_as_i32[2 * i + 1];
    nz = __syncthreads_or(nz);
    if (t == 0) g_idx_is_i64 = (nz == 0) ? 1 : 0;
}

// ---------------------------------------------------------------------------
// Kernel 1: transpose pos (B,3,N) channel-major -> (B*N) float4 xyz-interleaved.
// All reads coalesced (consecutive n), one float4 store per point.
// ---------------------------------------------------------------------------
__global__ void __launch_bounds__(256) transpose_pos_kernel(
    const float* __restrict__ pos)
{
    int i = blockIdx.x * 256 + threadIdx.x;     // exact grid, no bounds check
    int b = i >> 16;
    int n = i & (NPTS - 1);
    const float* p = pos + (size_t)b * 3 * NPTS;
    g_pos_t[i] = make_float4(__ldg(p + n),
                             __ldg(p + NPTS + n),
                             __ldg(p + 2 * NPTS + n), 0.0f);
}

// ---------------------------------------------------------------------------
// Kernel 2: main. 16 lanes per point (lane = neighbor k).
//   - idx load:  LDG.64 (or .32), warp covers 2 points -> 256B contiguous
//   - dist load: LDG.32, warp covers 128B contiguous
//   - gather:    one LDG.128 from g_pos_t per lane (random, L2-resident)
//   - max over K: 4x shfl.xor butterfly per channel (7 k-dependent channels)
//   - GEMV 10x64: each lane owns 4 output columns, W/b staged in shared
//   - store:     float4 per lane, warp writes 512B contiguous
// 256 threads/block = 16 points/block.
// ---------------------------------------------------------------------------
__global__ void __launch_bounds__(256) point_embed_kernel(
    const void*  __restrict__ idx_raw,
    const float* __restrict__ dist,
    const float* __restrict__ W,
    const float* __restrict__ bias,
    float*       __restrict__ out)
{
    __shared__ float sW[10 * HID];   // 2560 B
    __shared__ float sB[HID];        //  256 B

    const int tid = threadIdx.x;

    const int kl = tid & 15;                     // neighbor slot within point
    const int g  = blockIdx.x * 16 + (tid >> 4); // global point id (b*N + n)
    const int b  = g >> 16;
    const size_t gk = (((size_t)g) << 4) + kl;   // flat (point, k) index

    // --- start the long-latency dependency chain FIRST -----------------------
    // neighbor index (dtype decided by probe; uniform branch, both coalesced)
    int j;
    if (g_idx_is_i64) {
        j = (int)__ldg(((const long long*)idx_raw) + gk);
    } else {
        j = __ldg(((const int*)idx_raw) + gk);
    }
    const float dk = __ldg(dist + gk);

    // gather neighbor xyz: single 16B load, L2-resident table (depends on j)
    const float4 nb = __ldg(&g_pos_t[(b << 16) + j]);

    // center xyz (same address across the 16 lanes -> broadcast via L1)
    const float4 c = __ldg(&g_pos_t[g]);

    // --- stage W/b while the loads are in flight -----------------------------
    #pragma unroll
    for (int i = tid; i < 10 * HID; i += 256) sW[i] = __ldg(W + i);
    if (tid < HID) sB[tid] = __ldg(bias + tid);
    __syncthreads();

    // per-k candidates for channels 3..9
    float v3 = nb.x,        v4 = nb.y,        v5 = nb.z;
    float v6 = c.x - nb.x,  v7 = c.y - nb.y,  v8 = c.z - nb.z;
    float v9 = dk;

    // max over the 16 lanes of this point (xor 1,2,4,8 stays inside the group)
    #pragma unroll
    for (int s = 1; s < 16; s <<= 1) {
        v3 = fmaxf(v3, __shfl_xor_sync(0xffffffffu, v3, s));
        v4 = fmaxf(v4, __shfl_xor_sync(0xffffffffu, v4, s));
        v5 = fmaxf(v5, __shfl_xor_sync(0xffffffffu, v5, s));
        v6 = fmaxf(v6, __shfl_xor_sync(0xffffffffu, v6, s));
        v7 = fmaxf(v7, __shfl_xor_sync(0xffffffffu, v7, s));
        v8 = fmaxf(v8, __shfl_xor_sync(0xffffffffu, v8, s));
        v9 = fmaxf(v9, __shfl_xor_sync(0xffffffffu, v9, s));
    }

    // feat[10]; channels 0..2 are the (k-invariant) center coords
    float f[10];
    f[0] = c.x; f[1] = c.y; f[2] = c.z;
    f[3] = v3;  f[4] = v4;  f[5] = v5;
    f[6] = v6;  f[7] = v7;  f[8] = v8;  f[9] = v9;

    // GEMV: lane kl computes output columns [4*kl, 4*kl+4)
    const float4* sW4 = (const float4*)sW;   // [10][16] float4
    const float4* sB4 = (const float4*)sB;   // [16] float4
    float4 acc = sB4[kl];
    #pragma unroll
    for (int cc = 0; cc < 10; cc++) {
        float4 w = sW4[cc * 16 + kl];
        acc.x = fmaf(f[cc], w.x, acc.x);
        acc.y = fmaf(f[cc], w.y, acc.y);
        acc.z = fmaf(f[cc], w.z, acc.z);
        acc.w = fmaf(f[cc], w.w, acc.w);
    }
    acc.x = fmaxf(acc.x, 0.0f);
    acc.y = fmaxf(acc.y, 0.0f);
    acc.z = fmaxf(acc.z, 0.0f);
    acc.w = fmaxf(acc.w, 0.0f);

    // out[b][n][64]: warp writes 512 contiguous bytes
    ((float4*)out)[(size_t)g * (HID / 4) + kl] = acc;
}

// ---------------------------------------------------------------------------
extern "C" void kernel_launch(void* const* d_in, const int* in_sizes, int n_in,
                              void* d_out, int out_size) {
    const float* pos  = (const float*)d_in[0];   // (4, 3, 65536) f32
    const void*  idx  = d_in[1];                 // (4, 65536, 16) int64-or-int32
    const float* dist = (const float*)d_in[2];   // (4, 65536, 16) f32
    const float* W    = (const float*)d_in[3];   // (10, 64) f32
    const float* bias = (const float*)d_in[4];   // (64,) f32
    float* out = (float*)d_out;                  // (4, 65536, 64) f32

    (void)in_sizes; (void)n_in; (void)out_size;

    probe_idx_dtype_kernel<<<1, 256>>>((const int*)idx);
    transpose_pos_kernel<<<(BATCH * NPTS) / 256, 256>>>(pos);
    point_embed_kernel<<<(BATCH * NPTS) / 16, 256>>>(idx, dist, W, bias, out);
}